// round 2
// baseline (speedup 1.0000x reference)
#include <cuda_runtime.h>
#include <cuda_bf16.h>
#include <math.h>

// ---------------------------------------------------------------------------
// Problem constants
// ---------------------------------------------------------------------------
#define Bq   8
#define Tq   1024
#define Dm   1024
#define Hh   16
#define Ll   8
#define Vv   8192
#define HD   64            // head dim
#define BT   (Bq*Tq)       // 8192 rows

// ---------------------------------------------------------------------------
// Scratch (static device globals: allocation-guard safe)
// ---------------------------------------------------------------------------
__device__ float g_x[BT * Dm];        // residual stream
__device__ float g_h[BT * Dm];        // layernorm output / gemm input
__device__ float g_q[BT * Dm];
__device__ float g_k[BT * Dm];
__device__ float g_v[BT * Dm];
__device__ float g_y[BT * Dm];        // attention output
__device__ float g_m[BT * 2 * Dm];    // MLP hidden

// ---------------------------------------------------------------------------
// Embedding: x[b,t,:] = tok[idx[b,t],:] + gpos[ts[b],:] + pos[t,:]
// ---------------------------------------------------------------------------
__global__ __launch_bounds__(256) void embed_kernel(
    const int* __restrict__ idx, const int* __restrict__ ts,
    const float* __restrict__ tok, const float* __restrict__ pos,
    const float* __restrict__ gpos, float* __restrict__ x)
{
    long i = (long)blockIdx.x * 256 + threadIdx.x;   // over B*T*D
    int d = (int)(i % Dm);
    long bt = i / Dm;
    int t = (int)(bt % Tq);
    int b = (int)(bt / Tq);
    int tokid = idx[b * Tq + t];
    int tstep = ts[b];
    x[i] = tok[(long)tokid * Dm + d] + gpos[(long)tstep * Dm + d] + pos[(long)t * Dm + d];
}

// ---------------------------------------------------------------------------
// LayerNorm: one block per row, D = 1024
// ---------------------------------------------------------------------------
__global__ __launch_bounds__(256) void layernorm_kernel(
    const float* __restrict__ X, const float* __restrict__ w,
    const float* __restrict__ b, float* __restrict__ Y)
{
    int row = blockIdx.x;
    const float* x = X + (long)row * Dm;
    float*       y = Y + (long)row * Dm;
    int tid = threadIdx.x;

    int i = tid * 4;
    float4 v = *(const float4*)(x + i);
    float s  = v.x + v.y + v.z + v.w;
    float ss = v.x*v.x + v.y*v.y + v.z*v.z + v.w*v.w;

    __shared__ float rs[8], rss[8];
    #pragma unroll
    for (int m = 16; m; m >>= 1) {
        s  += __shfl_xor_sync(0xffffffffu, s,  m);
        ss += __shfl_xor_sync(0xffffffffu, ss, m);
    }
    int wid = tid >> 5, lane = tid & 31;
    if (lane == 0) { rs[wid] = s; rss[wid] = ss; }
    __syncthreads();
    if (wid == 0) {
        s  = (lane < 8) ? rs[lane]  : 0.f;
        ss = (lane < 8) ? rss[lane] : 0.f;
        #pragma unroll
        for (int m = 4; m; m >>= 1) {
            s  += __shfl_xor_sync(0xffffffffu, s,  m);
            ss += __shfl_xor_sync(0xffffffffu, ss, m);
        }
        if (lane == 0) { rs[0] = s; rss[0] = ss; }
    }
    __syncthreads();
    float mean = rs[0] * (1.0f / Dm);
    float var  = rss[0] * (1.0f / Dm) - mean * mean;
    float rstd = rsqrtf(var + 1e-5f);

    float4 wv = *(const float4*)(w + i);
    float4 bv = *(const float4*)(b + i);
    float4 o;
    o.x = (v.x - mean) * rstd * wv.x + bv.x;
    o.y = (v.y - mean) * rstd * wv.y + bv.y;
    o.z = (v.z - mean) * rstd * wv.z + bv.z;
    o.w = (v.w - mean) * rstd * wv.w + bv.w;
    *(float4*)(y + i) = o;
}

// ---------------------------------------------------------------------------
// NT SGEMM: C[m,n] = sum_k A[m,k]*B[n,k] (+bias) (+res) (gelu)
// A: [M,K] row-major, B: [N,K] row-major. M%128==0, N%128==0, K%8==0.
// Tile 128x128x8, thread tile 8x8, 256 threads.
// ---------------------------------------------------------------------------
#define EPI_NONE 0
#define EPI_ADD  1
#define EPI_GELU 2

template<int EPI>
__global__ __launch_bounds__(256) void gemm_nt(
    const float* __restrict__ A, const float* __restrict__ B,
    const float* __restrict__ bias, const float* __restrict__ res,
    float* __restrict__ C, int M, int N, int K)
{
    __shared__ float As[8][128];
    __shared__ float Bs[8][128];

    int tid = threadIdx.x;
    int m0 = blockIdx.y * 128;
    int n0 = blockIdx.x * 128;

    int lrow  = tid >> 1;            // 0..127
    int lcol4 = (tid & 1) << 2;      // 0 or 4
    int tx = tid & 15;               // n dir
    int ty = tid >> 4;               // m dir

    float acc[8][8];
    #pragma unroll
    for (int i = 0; i < 8; i++)
        #pragma unroll
        for (int j = 0; j < 8; j++) acc[i][j] = 0.f;

    const float* Aptr = A + (long)(m0 + lrow) * K + lcol4;
    const float* Bptr = B + (long)(n0 + lrow) * K + lcol4;

    for (int k0 = 0; k0 < K; k0 += 8) {
        float4 av = *(const float4*)(Aptr + k0);
        float4 bv = *(const float4*)(Bptr + k0);
        As[lcol4 + 0][lrow] = av.x; As[lcol4 + 1][lrow] = av.y;
        As[lcol4 + 2][lrow] = av.z; As[lcol4 + 3][lrow] = av.w;
        Bs[lcol4 + 0][lrow] = bv.x; Bs[lcol4 + 1][lrow] = bv.y;
        Bs[lcol4 + 2][lrow] = bv.z; Bs[lcol4 + 3][lrow] = bv.w;
        __syncthreads();

        #pragma unroll
        for (int kk = 0; kk < 8; kk++) {
            float4 a0 = *(const float4*)&As[kk][ty * 8];
            float4 a1 = *(const float4*)&As[kk][ty * 8 + 4];
            float4 b0 = *(const float4*)&Bs[kk][tx * 8];
            float4 b1 = *(const float4*)&Bs[kk][tx * 8 + 4];
            float af[8] = {a0.x, a0.y, a0.z, a0.w, a1.x, a1.y, a1.z, a1.w};
            float bf[8] = {b0.x, b0.y, b0.z, b0.w, b1.x, b1.y, b1.z, b1.w};
            #pragma unroll
            for (int i = 0; i < 8; i++)
                #pragma unroll
                for (int j = 0; j < 8; j++)
                    acc[i][j] = fmaf(af[i], bf[j], acc[i][j]);
        }
        __syncthreads();
    }

    #pragma unroll
    for (int i = 0; i < 8; i++) {
        long row = m0 + ty * 8 + i;
        #pragma unroll
        for (int j = 0; j < 8; j++) {
            int col = n0 + tx * 8 + j;
            float val = acc[i][j] + (bias ? bias[col] : 0.f);
            if (EPI == EPI_ADD)  val += res[row * N + col];
            if (EPI == EPI_GELU) val = 0.5f * val * (1.f + erff(val * 0.70710678118654752f));
            C[row * N + col] = val;
        }
    }
}

// ---------------------------------------------------------------------------
// Flash attention (fp32, causal). Q/K/V layout [B, T, D] with head slice
// h*64..h*64+63.  Block = (qt, h, b); 64 q-rows per block; online softmax.
// Row padding 68 floats (272 B) keeps every float4 row base 16B-aligned.
// ---------------------------------------------------------------------------
#define APAD 68
#define ATT_SMEM_FLOATS (4 * 64 * APAD)

__global__ __launch_bounds__(256) void attn_kernel(
    const float* __restrict__ Q, const float* __restrict__ K,
    const float* __restrict__ V, float* __restrict__ Y)
{
    extern __shared__ float smem[];
    float (*Qs)[APAD]  = (float (*)[APAD])(smem);                  // [qrow][hd]
    float (*Kst)[APAD] = (float (*)[APAD])(smem + 64 * APAD);      // [hd][krow]
    float (*Vs)[APAD]  = (float (*)[APAD])(smem + 2 * 64 * APAD);  // [krow][hd]
    float (*Ps)[APAD]  = (float (*)[APAD])(smem + 3 * 64 * APAD);  // [qrow][krow]

    const int qt = blockIdx.x, h = blockIdx.y, b = blockIdx.z;
    const int tid = threadIdx.x;
    const int tx = tid & 15;   // col group
    const int ty = tid >> 4;   // row group

    const long baseq = ((long)(b * Tq + qt * 64)) * Dm + h * HD;

    for (int i = tid; i < 64 * 16; i += 256) {
        int r = i >> 4, c4 = (i & 15) << 2;
        float4 v = *(const float4*)(Q + baseq + (long)r * Dm + c4);
        Qs[r][c4] = v.x; Qs[r][c4 + 1] = v.y; Qs[r][c4 + 2] = v.z; Qs[r][c4 + 3] = v.w;
    }

    float m_i[4], l_i[4], o[4][4];
    #pragma unroll
    for (int i = 0; i < 4; i++) {
        m_i[i] = -1e30f; l_i[i] = 0.f;
        #pragma unroll
        for (int j = 0; j < 4; j++) o[i][j] = 0.f;
    }

    for (int kt = 0; kt <= qt; kt++) {
        const long basek = ((long)(b * Tq + kt * 64)) * Dm + h * HD;
        for (int i = tid; i < 64 * 16; i += 256) {
            int r = i >> 4, c4 = (i & 15) << 2;
            float4 kv = *(const float4*)(K + basek + (long)r * Dm + c4);
            Kst[c4][r] = kv.x; Kst[c4 + 1][r] = kv.y; Kst[c4 + 2][r] = kv.z; Kst[c4 + 3][r] = kv.w;
            float4 vv = *(const float4*)(V + basek + (long)r * Dm + c4);
            Vs[r][c4] = vv.x; Vs[r][c4 + 1] = vv.y; Vs[r][c4 + 2] = vv.z; Vs[r][c4 + 3] = vv.w;
        }
        __syncthreads();

        // S[r][c] = sum_kk Qs[r][kk] * Kst[kk][c]
        float s[4][4];
        #pragma unroll
        for (int i = 0; i < 4; i++)
            #pragma unroll
            for (int j = 0; j < 4; j++) s[i][j] = 0.f;

        #pragma unroll 8
        for (int kk = 0; kk < 64; kk++) {
            float a0 = Qs[4 * ty + 0][kk];
            float a1 = Qs[4 * ty + 1][kk];
            float a2 = Qs[4 * ty + 2][kk];
            float a3 = Qs[4 * ty + 3][kk];
            float4 bb = *(const float4*)&Kst[kk][4 * tx];
            s[0][0] = fmaf(a0, bb.x, s[0][0]); s[0][1] = fmaf(a0, bb.y, s[0][1]);
            s[0][2] = fmaf(a0, bb.z, s[0][2]); s[0][3] = fmaf(a0, bb.w, s[0][3]);
            s[1][0] = fmaf(a1, bb.x, s[1][0]); s[1][1] = fmaf(a1, bb.y, s[1][1]);
            s[1][2] = fmaf(a1, bb.z, s[1][2]); s[1][3] = fmaf(a1, bb.w, s[1][3]);
            s[2][0] = fmaf(a2, bb.x, s[2][0]); s[2][1] = fmaf(a2, bb.y, s[2][1]);
            s[2][2] = fmaf(a2, bb.z, s[2][2]); s[2][3] = fmaf(a2, bb.w, s[2][3]);
            s[3][0] = fmaf(a3, bb.x, s[3][0]); s[3][1] = fmaf(a3, bb.y, s[3][1]);
            s[3][2] = fmaf(a3, bb.z, s[3][2]); s[3][3] = fmaf(a3, bb.w, s[3][3]);
        }

        const float scale = 0.125f;   // 1/sqrt(64)
        #pragma unroll
        for (int i = 0; i < 4; i++)
            #pragma unroll
            for (int j = 0; j < 4; j++) s[i][j] *= scale;

        if (kt == qt) {
            #pragma unroll
            for (int i = 0; i < 4; i++)
                #pragma unroll
                for (int j = 0; j < 4; j++)
                    if (4 * tx + j > 4 * ty + i) s[i][j] = -1e30f;
        }

        // online softmax: rows 4*ty+i, 16 lanes (tx) share a row
        #pragma unroll
        for (int i = 0; i < 4; i++) {
            float rmax = fmaxf(fmaxf(s[i][0], s[i][1]), fmaxf(s[i][2], s[i][3]));
            #pragma unroll
            for (int m = 8; m; m >>= 1)
                rmax = fmaxf(rmax, __shfl_xor_sync(0xffffffffu, rmax, m));
            float mnew  = fmaxf(m_i[i], rmax);
            float alpha = expf(m_i[i] - mnew);
            m_i[i] = mnew;
            float rsum = 0.f;
            #pragma unroll
            for (int j = 0; j < 4; j++) {
                float p = expf(s[i][j] - mnew);
                s[i][j] = p;
                rsum += p;
            }
            #pragma unroll
            for (int m = 8; m; m >>= 1)
                rsum += __shfl_xor_sync(0xffffffffu, rsum, m);
            l_i[i] = l_i[i] * alpha + rsum;
            #pragma unroll
            for (int j = 0; j < 4; j++) o[i][j] *= alpha;
        }

        #pragma unroll
        for (int i = 0; i < 4; i++)
            #pragma unroll
            for (int j = 0; j < 4; j++)
                Ps[4 * ty + i][4 * tx + j] = s[i][j];
        __syncthreads();

        // O += Ps @ Vs
        #pragma unroll 8
        for (int kk = 0; kk < 64; kk++) {
            float a0 = Ps[4 * ty + 0][kk];
            float a1 = Ps[4 * ty + 1][kk];
            float a2 = Ps[4 * ty + 2][kk];
            float a3 = Ps[4 * ty + 3][kk];
            float4 bb = *(const float4*)&Vs[kk][4 * tx];
            o[0][0] = fmaf(a0, bb.x, o[0][0]); o[0][1] = fmaf(a0, bb.y, o[0][1]);
            o[0][2] = fmaf(a0, bb.z, o[0][2]); o[0][3] = fmaf(a0, bb.w, o[0][3]);
            o[1][0] = fmaf(a1, bb.x, o[1][0]); o[1][1] = fmaf(a1, bb.y, o[1][1]);
            o[1][2] = fmaf(a1, bb.z, o[1][2]); o[1][3] = fmaf(a1, bb.w, o[1][3]);
            o[2][0] = fmaf(a2, bb.x, o[2][0]); o[2][1] = fmaf(a2, bb.y, o[2][1]);
            o[2][2] = fmaf(a2, bb.z, o[2][2]); o[2][3] = fmaf(a2, bb.w, o[2][3]);
            o[3][0] = fmaf(a3, bb.x, o[3][0]); o[3][1] = fmaf(a3, bb.y, o[3][1]);
            o[3][2] = fmaf(a3, bb.z, o[3][2]); o[3][3] = fmaf(a3, bb.w, o[3][3]);
        }
        __syncthreads();
    }

    #pragma unroll
    for (int i = 0; i < 4; i++) {
        float inv = 1.f / l_i[i];
        long orow = baseq + (long)(4 * ty + i) * Dm + 4 * tx;
        Y[orow + 0] = o[i][0] * inv;
        Y[orow + 1] = o[i][1] * inv;
        Y[orow + 2] = o[i][2] * inv;
        Y[orow + 3] = o[i][3] * inv;
    }
}

// ---------------------------------------------------------------------------
// Launcher
// ---------------------------------------------------------------------------
extern "C" void kernel_launch(void* const* d_in, const int* in_sizes, int n_in,
                              void* d_out, int out_size)
{
    const int*   idx  = (const int*)  d_in[0];
    const int*   ts   = (const int*)  d_in[1];
    const float* tok  = (const float*)d_in[2];
    const float* pos  = (const float*)d_in[3];
    const float* gpos = (const float*)d_in[4];
    const float* ln1w = (const float*)d_in[5];
    const float* ln1b = (const float*)d_in[6];
    const float* Wq   = (const float*)d_in[7];
    const float* bq   = (const float*)d_in[8];
    const float* Wk   = (const float*)d_in[9];
    const float* bk   = (const float*)d_in[10];
    const float* Wv   = (const float*)d_in[11];
    const float* bv   = (const float*)d_in[12];
    const float* Wo   = (const float*)d_in[13];
    const float* bo   = (const float*)d_in[14];
    const float* ln2w = (const float*)d_in[15];
    const float* ln2b = (const float*)d_in[16];
    const float* W1   = (const float*)d_in[17];
    const float* b1   = (const float*)d_in[18];
    const float* W2   = (const float*)d_in[19];
    const float* b2   = (const float*)d_in[20];
    const float* lnfw = (const float*)d_in[21];
    const float* lnfb = (const float*)d_in[22];
    const float* hw   = (const float*)d_in[23];
    float* out = (float*)d_out;

    float *x, *h, *q, *k, *v, *y, *mb;
    cudaGetSymbolAddress((void**)&x,  g_x);
    cudaGetSymbolAddress((void**)&h,  g_h);
    cudaGetSymbolAddress((void**)&q,  g_q);
    cudaGetSymbolAddress((void**)&k,  g_k);
    cudaGetSymbolAddress((void**)&v,  g_v);
    cudaGetSymbolAddress((void**)&y,  g_y);
    cudaGetSymbolAddress((void**)&mb, g_m);

    cudaFuncSetAttribute(attn_kernel, cudaFuncAttributeMaxDynamicSharedMemorySize,
                         ATT_SMEM_FLOATS * (int)sizeof(float));

    // embeddings
    embed_kernel<<<(BT * Dm) / 256, 256>>>(idx, ts, tok, pos, gpos, x);

    const dim3 gD(Dm / 128, BT / 128);      // N=1024 GEMMs
    const dim3 g2D(2 * Dm / 128, BT / 128); // N=2048 (W1)
    const dim3 gV(Vv / 128, BT / 128);      // head

    for (int l = 0; l < Ll; l++) {
        layernorm_kernel<<<BT, 256>>>(x, ln1w + (long)l * Dm, ln1b + (long)l * Dm, h);

        gemm_nt<EPI_NONE><<<gD, 256>>>(h, Wq + (long)l * Dm * Dm, bq + (long)l * Dm,
                                       nullptr, q, BT, Dm, Dm);
        gemm_nt<EPI_NONE><<<gD, 256>>>(h, Wk + (long)l * Dm * Dm, bk + (long)l * Dm,
                                       nullptr, k, BT, Dm, Dm);
        gemm_nt<EPI_NONE><<<gD, 256>>>(h, Wv + (long)l * Dm * Dm, bv + (long)l * Dm,
                                       nullptr, v, BT, Dm, Dm);

        attn_kernel<<<dim3(Tq / 64, Hh, Bq), 256,
                      ATT_SMEM_FLOATS * sizeof(float)>>>(q, k, v, y);

        gemm_nt<EPI_ADD><<<gD, 256>>>(y, Wo + (long)l * Dm * Dm, bo + (long)l * Dm,
                                      x, x, BT, Dm, Dm);

        layernorm_kernel<<<BT, 256>>>(x, ln2w + (long)l * Dm, ln2b + (long)l * Dm, h);

        gemm_nt<EPI_GELU><<<g2D, 256>>>(h, W1 + (long)l * 2 * Dm * Dm, b1 + (long)l * 2 * Dm,
                                        nullptr, mb, BT, 2 * Dm, Dm);
        gemm_nt<EPI_ADD><<<gD, 256>>>(mb, W2 + (long)l * Dm * 2 * Dm, b2 + (long)l * Dm,
                                      x, x, BT, Dm, 2 * Dm);
    }

    layernorm_kernel<<<BT, 256>>>(x, lnfw, lnfb, h);
    gemm_nt<EPI_NONE><<<gV, 256>>>(h, hw, nullptr, nullptr, out, BT, Vv, Dm);
}

// round 4
// speedup vs baseline: 2.2545x; 2.2545x over previous
#include <cuda_runtime.h>
#include <cuda_fp16.h>
#include <math.h>
#include <stdint.h>

// ---------------------------------------------------------------------------
// Problem constants
// ---------------------------------------------------------------------------
#define Bq   8
#define Tq   1024
#define Dm   1024
#define Hh   16
#define Ll   8
#define Vv   8192
#define HD   64
#define BT   (Bq*Tq)

// ---------------------------------------------------------------------------
// Scratch (static device globals)
// ---------------------------------------------------------------------------
__device__ float g_x[BT * Dm];        // residual stream (f32)
__device__ float g_q[BT * Dm];
__device__ float g_k[BT * Dm];
__device__ float g_v[BT * Dm];

__device__ __half g_pa_h[BT * Dm];       // pair buf A: LN out / attn out
__device__ __half g_pa_l[BT * Dm];
__device__ __half g_pb_h[BT * 2 * Dm];   // pair buf B: MLP hidden (gelu out)
__device__ __half g_pb_l[BT * 2 * Dm];

#define DD      (Dm*Dm)                  // 1M
#define OFF_WQ  0L
#define OFF_WK  (8L*DD)
#define OFF_WV  (16L*DD)
#define OFF_WO  (24L*DD)
#define OFF_W1  (32L*DD)
#define OFF_W2  (48L*DD)
#define OFF_HW  (64L*DD)
#define WTOT    (72L*DD)
__device__ __half g_wh[WTOT];            // weight hi
__device__ __half g_wl[WTOT];            // weight lo

// ---------------------------------------------------------------------------
// Small helpers
// ---------------------------------------------------------------------------
__device__ __forceinline__ uint32_t smem_u32(const void* p) {
    uint32_t a;
    asm("{ .reg .u64 t; cvta.to.shared.u64 t, %1; cvt.u32.u64 %0, t; }"
        : "=r"(a) : "l"(p));
    return a;
}
__device__ __forceinline__ uint32_t lds32(uint32_t a) {
    uint32_t v; asm volatile("ld.shared.b32 %0, [%1];" : "=r"(v) : "r"(a));
    return v;
}
__device__ __forceinline__ void cpa16(uint32_t dst, const void* src) {
    asm volatile("cp.async.cg.shared.global [%0], [%1], 16;" :: "r"(dst), "l"(src));
}
__device__ __forceinline__ void mma_f16(float& d0, float& d1, float& d2, float& d3,
                                        uint32_t a0, uint32_t a1, uint32_t a2, uint32_t a3,
                                        uint32_t b0, uint32_t b1) {
    asm volatile(
        "mma.sync.aligned.m16n8k16.row.col.f32.f16.f16.f32 "
        "{%0,%1,%2,%3}, {%4,%5,%6,%7}, {%8,%9}, {%0,%1,%2,%3};"
        : "+f"(d0), "+f"(d1), "+f"(d2), "+f"(d3)
        : "r"(a0), "r"(a1), "r"(a2), "r"(a3), "r"(b0), "r"(b1));
}
__device__ __forceinline__ void split16(float x, __half& hi, __half& lo) {
    hi = __float2half_rn(x);
    lo = __float2half_rn(x - __half2float(hi));
}

// ---------------------------------------------------------------------------
// Weight f32 -> f16 hi/lo pair conversion
// ---------------------------------------------------------------------------
__global__ __launch_bounds__(256) void cvt_pair(
    const float* __restrict__ s, __half* __restrict__ h,
    __half* __restrict__ l, long n)
{
    long i = ((long)blockIdx.x * 256 + threadIdx.x) * 4;
    if (i >= n) return;
    float4 v = *(const float4*)(s + i);
    __half h0, h1, h2, h3, l0, l1, l2, l3;
    split16(v.x, h0, l0); split16(v.y, h1, l1);
    split16(v.z, h2, l2); split16(v.w, h3, l3);
    *(__half2*)(h + i)     = __halves2half2(h0, h1);
    *(__half2*)(h + i + 2) = __halves2half2(h2, h3);
    *(__half2*)(l + i)     = __halves2half2(l0, l1);
    *(__half2*)(l + i + 2) = __halves2half2(l2, l3);
}

// ---------------------------------------------------------------------------
// Embedding
// ---------------------------------------------------------------------------
__global__ __launch_bounds__(256) void embed_kernel(
    const int* __restrict__ idx, const int* __restrict__ ts,
    const float* __restrict__ tok, const float* __restrict__ pos,
    const float* __restrict__ gpos, float* __restrict__ x)
{
    long i = (long)blockIdx.x * 256 + threadIdx.x;
    int d = (int)(i % Dm);
    long bt = i / Dm;
    int t = (int)(bt % Tq);
    int b = (int)(bt / Tq);
    int tokid = idx[b * Tq + t];
    int tstep = ts[b];
    x[i] = tok[(long)tokid * Dm + d] + gpos[(long)tstep * Dm + d] + pos[(long)t * Dm + d];
}

// ---------------------------------------------------------------------------
// LayerNorm -> f16 hi/lo pair output
// ---------------------------------------------------------------------------
__global__ __launch_bounds__(256) void layernorm_pair(
    const float* __restrict__ X, const float* __restrict__ w,
    const float* __restrict__ b, __half* __restrict__ Yh, __half* __restrict__ Yl)
{
    int row = blockIdx.x;
    const float* x = X + (long)row * Dm;
    int tid = threadIdx.x;

    int i = tid * 4;
    float4 v = *(const float4*)(x + i);
    float s  = v.x + v.y + v.z + v.w;
    float ss = v.x*v.x + v.y*v.y + v.z*v.z + v.w*v.w;

    __shared__ float rs[8], rss[8];
    #pragma unroll
    for (int m = 16; m; m >>= 1) {
        s  += __shfl_xor_sync(0xffffffffu, s,  m);
        ss += __shfl_xor_sync(0xffffffffu, ss, m);
    }
    int wid = tid >> 5, lane = tid & 31;
    if (lane == 0) { rs[wid] = s; rss[wid] = ss; }
    __syncthreads();
    if (wid == 0) {
        s  = (lane < 8) ? rs[lane]  : 0.f;
        ss = (lane < 8) ? rss[lane] : 0.f;
        #pragma unroll
        for (int m = 4; m; m >>= 1) {
            s  += __shfl_xor_sync(0xffffffffu, s,  m);
            ss += __shfl_xor_sync(0xffffffffu, ss, m);
        }
        if (lane == 0) { rs[0] = s; rss[0] = ss; }
    }
    __syncthreads();
    float mean = rs[0] * (1.0f / Dm);
    float var  = rss[0] * (1.0f / Dm) - mean * mean;
    float rstd = rsqrtf(var + 1e-5f);

    float4 wv = *(const float4*)(w + i);
    float4 bv = *(const float4*)(b + i);
    float o0 = (v.x - mean) * rstd * wv.x + bv.x;
    float o1 = (v.y - mean) * rstd * wv.y + bv.y;
    float o2 = (v.z - mean) * rstd * wv.z + bv.z;
    float o3 = (v.w - mean) * rstd * wv.w + bv.w;

    long base = (long)row * Dm + i;
    __half h0, h1, h2, h3, l0, l1, l2, l3;
    split16(o0, h0, l0); split16(o1, h1, l1);
    split16(o2, h2, l2); split16(o3, h3, l3);
    *(__half2*)(Yh + base)     = __halves2half2(h0, h1);
    *(__half2*)(Yh + base + 2) = __halves2half2(h2, h3);
    *(__half2*)(Yl + base)     = __halves2half2(l0, l1);
    *(__half2*)(Yl + base + 2) = __halves2half2(l2, l3);
}

// ---------------------------------------------------------------------------
// HMMA GEMM (3x f16 split): C[m,n] = sum_k A[m,k]*B[n,k] (+bias)(+res | gelu->pair)
// A,B given as f16 hi/lo pairs, K-major. CTA tile 128x128, k-step 32,
// cp.async double-buffered. 8 warps, warp tile 64x32 (m x n).
// smem: 2 stages x 4 tiles x [128 rows x 40 halfs] = 81920 B.
// ---------------------------------------------------------------------------
#define EPI_NONE 0
#define EPI_ADD  1
#define EPI_GELU 2

#define PK      40
#define TILE_H  (128*PK)        // halfs per tile (5120)
#define STG_H   (4*TILE_H)      // halfs per stage (20480)
#define GEMM_SMEM (2*STG_H*2)   // bytes (81920)

template<int EPI>
__global__ __launch_bounds__(256, 2) void gemm_hmma(
    const __half* __restrict__ Ah, const __half* __restrict__ Al,
    const __half* __restrict__ Bh, const __half* __restrict__ Bl,
    const float* __restrict__ bias, const float* __restrict__ res,
    float* __restrict__ C, __half* __restrict__ Ch, __half* __restrict__ Cl,
    int M, int N, int K)
{
    extern __shared__ __align__(16) __half gsm[];
    const uint32_t sbase = smem_u32(gsm);

    const int tid = threadIdx.x, lane = tid & 31, warp = tid >> 5;
    const int g = lane >> 2, t = lane & 3;
    const int wm = warp & 1, wn = warp >> 1;
    const int m0 = blockIdx.y * 128, n0 = blockIdx.x * 128;

    float acc[4][4][4];
    #pragma unroll
    for (int a = 0; a < 4; a++)
        #pragma unroll
        for (int b = 0; b < 4; b++)
            #pragma unroll
            for (int c = 0; c < 4; c++) acc[a][b][c] = 0.f;

    const int S = K >> 5;

    // --- stage issue: 2048 16B chunks, 8 per thread ---
    auto issue = [&](int k0, int buf) {
        #pragma unroll
        for (int j = 0; j < 8; j++) {
            int c = tid + 256 * j;
            int tile = c >> 9;              // 0..3
            int r = (c >> 2) & 127;
            int q = c & 3;
            const __half* src;
            if      (tile == 0) src = Ah + (long)(m0 + r) * K + k0 + q * 8;
            else if (tile == 1) src = Al + (long)(m0 + r) * K + k0 + q * 8;
            else if (tile == 2) src = Bh + (long)(n0 + r) * K + k0 + q * 8;
            else                src = Bl + (long)(n0 + r) * K + k0 + q * 8;
            uint32_t dst = sbase + (uint32_t)(buf * STG_H + tile * TILE_H + r * PK + q * 8) * 2u;
            cpa16(dst, src);
        }
        asm volatile("cp.async.commit_group;" ::: "memory");
    };

    issue(0, 0);

    for (int s = 0; s < S; s++) {
        asm volatile("cp.async.wait_group 0;" ::: "memory");
        __syncthreads();
        if (s + 1 < S) issue((s + 1) << 5, (s + 1) & 1);

        uint32_t sb  = sbase + (uint32_t)((s & 1) * STG_H) * 2u;
        uint32_t A_h = sb;
        uint32_t A_l = sb + TILE_H * 2u;
        uint32_t B_h = sb + 2u * TILE_H * 2u;
        uint32_t B_l = sb + 3u * TILE_H * 2u;

        #pragma unroll
        for (int kk = 0; kk < 32; kk += 16) {
            uint32_t bh[4][2], bl[4][2];
            #pragma unroll
            for (int ni = 0; ni < 4; ni++) {
                uint32_t off = (uint32_t)((wn * 32 + ni * 8 + g) * PK + kk + 2 * t) * 2u;
                bh[ni][0] = lds32(B_h + off); bh[ni][1] = lds32(B_h + off + 16);
                bl[ni][0] = lds32(B_l + off); bl[ni][1] = lds32(B_l + off + 16);
            }
            #pragma unroll
            for (int mi = 0; mi < 4; mi++) {
                uint32_t off0 = (uint32_t)((wm * 64 + mi * 16 + g) * PK + kk + 2 * t) * 2u;
                uint32_t off1 = off0 + 8 * PK * 2;
                uint32_t ah0 = lds32(A_h + off0),     ah1 = lds32(A_h + off1);
                uint32_t ah2 = lds32(A_h + off0 + 16), ah3 = lds32(A_h + off1 + 16);
                uint32_t al0 = lds32(A_l + off0),     al1 = lds32(A_l + off1);
                uint32_t al2 = lds32(A_l + off0 + 16), al3 = lds32(A_l + off1 + 16);
                #pragma unroll
                for (int ni = 0; ni < 4; ni++) {
                    float* d = acc[mi][ni];
                    mma_f16(d[0], d[1], d[2], d[3], ah0, ah1, ah2, ah3, bh[ni][0], bh[ni][1]);
                    mma_f16(d[0], d[1], d[2], d[3], ah0, ah1, ah2, ah3, bl[ni][0], bl[ni][1]);
                    mma_f16(d[0], d[1], d[2], d[3], al0, al1, al2, al3, bh[ni][0], bh[ni][1]);
                }
            }
        }
    }

    // --- epilogue ---
    #pragma unroll
    for (int mi = 0; mi < 4; mi++) {
        int r0 = m0 + wm * 64 + mi * 16 + g;
        #pragma unroll
        for (int ni = 0; ni < 4; ni++) {
            int cc = n0 + wn * 32 + ni * 8 + 2 * t;
            float b0v = bias ? bias[cc] : 0.f;
            float b1v = bias ? bias[cc + 1] : 0.f;
            float v0 = acc[mi][ni][0] + b0v, v1 = acc[mi][ni][1] + b1v;
            float v2 = acc[mi][ni][2] + b0v, v3 = acc[mi][ni][3] + b1v;
            long i0 = (long)r0 * N + cc;
            long i1 = (long)(r0 + 8) * N + cc;
            if (EPI == EPI_ADD) {
                v0 += res[i0]; v1 += res[i0 + 1];
                v2 += res[i1]; v3 += res[i1 + 1];
            }
            if (EPI == EPI_GELU) {
                v0 = 0.5f * v0 * (1.f + erff(v0 * 0.70710678118654752f));
                v1 = 0.5f * v1 * (1.f + erff(v1 * 0.70710678118654752f));
                v2 = 0.5f * v2 * (1.f + erff(v2 * 0.70710678118654752f));
                v3 = 0.5f * v3 * (1.f + erff(v3 * 0.70710678118654752f));
                __half h0, h1, h2, h3, l0, l1, l2, l3;
                split16(v0, h0, l0); split16(v1, h1, l1);
                split16(v2, h2, l2); split16(v3, h3, l3);
                *(__half2*)(Ch + i0) = __halves2half2(h0, h1);
                *(__half2*)(Ch + i1) = __halves2half2(h2, h3);
                *(__half2*)(Cl + i0) = __halves2half2(l0, l1);
                *(__half2*)(Cl + i1) = __halves2half2(l2, l3);
            } else {
                *(float2*)(C + i0) = make_float2(v0, v1);
                *(float2*)(C + i1) = make_float2(v2, v3);
            }
        }
    }
}

// ---------------------------------------------------------------------------
// Flash attention (fp32, causal) -> f16 hi/lo pair output
// ---------------------------------------------------------------------------
#define APAD 68
#define ATT_SMEM_FLOATS (4 * 64 * APAD)

__global__ __launch_bounds__(256) void attn_kernel(
    const float* __restrict__ Q, const float* __restrict__ K,
    const float* __restrict__ V, __half* __restrict__ Yh, __half* __restrict__ Yl)
{
    extern __shared__ float smem[];
    float (*Qs)[APAD]  = (float (*)[APAD])(smem);
    float (*Kst)[APAD] = (float (*)[APAD])(smem + 64 * APAD);
    float (*Vs)[APAD]  = (float (*)[APAD])(smem + 2 * 64 * APAD);
    float (*Ps)[APAD]  = (float (*)[APAD])(smem + 3 * 64 * APAD);

    const int qt = blockIdx.x, h = blockIdx.y, b = blockIdx.z;
    const int tid = threadIdx.x;
    const int tx = tid & 15;
    const int ty = tid >> 4;

    const long baseq = ((long)(b * Tq + qt * 64)) * Dm + h * HD;

    for (int i = tid; i < 64 * 16; i += 256) {
        int r = i >> 4, c4 = (i & 15) << 2;
        float4 v = *(const float4*)(Q + baseq + (long)r * Dm + c4);
        Qs[r][c4] = v.x; Qs[r][c4 + 1] = v.y; Qs[r][c4 + 2] = v.z; Qs[r][c4 + 3] = v.w;
    }

    float m_i[4], l_i[4], o[4][4];
    #pragma unroll
    for (int i = 0; i < 4; i++) {
        m_i[i] = -1e30f; l_i[i] = 0.f;
        #pragma unroll
        for (int j = 0; j < 4; j++) o[i][j] = 0.f;
    }

    for (int kt = 0; kt <= qt; kt++) {
        const long basek = ((long)(b * Tq + kt * 64)) * Dm + h * HD;
        for (int i = tid; i < 64 * 16; i += 256) {
            int r = i >> 4, c4 = (i & 15) << 2;
            float4 kv = *(const float4*)(K + basek + (long)r * Dm + c4);
            Kst[c4][r] = kv.x; Kst[c4 + 1][r] = kv.y; Kst[c4 + 2][r] = kv.z; Kst[c4 + 3][r] = kv.w;
            float4 vv = *(const float4*)(V + basek + (long)r * Dm + c4);
            Vs[r][c4] = vv.x; Vs[r][c4 + 1] = vv.y; Vs[r][c4 + 2] = vv.z; Vs[r][c4 + 3] = vv.w;
        }
        __syncthreads();

        float s[4][4];
        #pragma unroll
        for (int i = 0; i < 4; i++)
            #pragma unroll
            for (int j = 0; j < 4; j++) s[i][j] = 0.f;

        #pragma unroll 8
        for (int kk = 0; kk < 64; kk++) {
            float a0 = Qs[4 * ty + 0][kk];
            float a1 = Qs[4 * ty + 1][kk];
            float a2 = Qs[4 * ty + 2][kk];
            float a3 = Qs[4 * ty + 3][kk];
            float4 bb = *(const float4*)&Kst[kk][4 * tx];
            s[0][0] = fmaf(a0, bb.x, s[0][0]); s[0][1] = fmaf(a0, bb.y, s[0][1]);
            s[0][2] = fmaf(a0, bb.z, s[0][2]); s[0][3] = fmaf(a0, bb.w, s[0][3]);
            s[1][0] = fmaf(a1, bb.x, s[1][0]); s[1][1] = fmaf(a1, bb.y, s[1][1]);
            s[1][2] = fmaf(a1, bb.z, s[1][2]); s[1][3] = fmaf(a1, bb.w, s[1][3]);
            s[2][0] = fmaf(a2, bb.x, s[2][0]); s[2][1] = fmaf(a2, bb.y, s[2][1]);
            s[2][2] = fmaf(a2, bb.z, s[2][2]); s[2][3] = fmaf(a2, bb.w, s[2][3]);
            s[3][0] = fmaf(a3, bb.x, s[3][0]); s[3][1] = fmaf(a3, bb.y, s[3][1]);
            s[3][2] = fmaf(a3, bb.z, s[3][2]); s[3][3] = fmaf(a3, bb.w, s[3][3]);
        }

        const float scale = 0.125f;
        #pragma unroll
        for (int i = 0; i < 4; i++)
            #pragma unroll
            for (int j = 0; j < 4; j++) s[i][j] *= scale;

        if (kt == qt) {
            #pragma unroll
            for (int i = 0; i < 4; i++)
                #pragma unroll
                for (int j = 0; j < 4; j++)
                    if (4 * tx + j > 4 * ty + i) s[i][j] = -1e30f;
        }

        #pragma unroll
        for (int i = 0; i < 4; i++) {
            float rmax = fmaxf(fmaxf(s[i][0], s[i][1]), fmaxf(s[i][2], s[i][3]));
            #pragma unroll
            for (int m = 8; m; m >>= 1)
                rmax = fmaxf(rmax, __shfl_xor_sync(0xffffffffu, rmax, m));
            float mnew  = fmaxf(m_i[i], rmax);
            float alpha = expf(m_i[i] - mnew);
            m_i[i] = mnew;
            float rsum = 0.f;
            #pragma unroll
            for (int j = 0; j < 4; j++) {
                float p = expf(s[i][j] - mnew);
                s[i][j] = p;
                rsum += p;
            }
            #pragma unroll
            for (int m = 8; m; m >>= 1)
                rsum += __shfl_xor_sync(0xffffffffu, rsum, m);
            l_i[i] = l_i[i] * alpha + rsum;
            #pragma unroll
            for (int j = 0; j < 4; j++) o[i][j] *= alpha;
        }

        #pragma unroll
        for (int i = 0; i < 4; i++)
            #pragma unroll
            for (int j = 0; j < 4; j++)
                Ps[4 * ty + i][4 * tx + j] = s[i][j];
        __syncthreads();

        #pragma unroll 8
        for (int kk = 0; kk < 64; kk++) {
            float a0 = Ps[4 * ty + 0][kk];
            float a1 = Ps[4 * ty + 1][kk];
            float a2 = Ps[4 * ty + 2][kk];
            float a3 = Ps[4 * ty + 3][kk];
            float4 bb = *(const float4*)&Vs[kk][4 * tx];
            o[0][0] = fmaf(a0, bb.x, o[0][0]); o[0][1] = fmaf(a0, bb.y, o[0][1]);
            o[0][2] = fmaf(a0, bb.z, o[0][2]); o[0][3] = fmaf(a0, bb.w, o[0][3]);
            o[1][0] = fmaf(a1, bb.x, o[1][0]); o[1][1] = fmaf(a1, bb.y, o[1][1]);
            o[1][2] = fmaf(a1, bb.z, o[1][2]); o[1][3] = fmaf(a1, bb.w, o[1][3]);
            o[2][0] = fmaf(a2, bb.x, o[2][0]); o[2][1] = fmaf(a2, bb.y, o[2][1]);
            o[2][2] = fmaf(a2, bb.z, o[2][2]); o[2][3] = fmaf(a2, bb.w, o[2][3]);
            o[3][0] = fmaf(a3, bb.x, o[3][0]); o[3][1] = fmaf(a3, bb.y, o[3][1]);
            o[3][2] = fmaf(a3, bb.z, o[3][2]); o[3][3] = fmaf(a3, bb.w, o[3][3]);
        }
        __syncthreads();
    }

    #pragma unroll
    for (int i = 0; i < 4; i++) {
        float inv = 1.f / l_i[i];
        long orow = baseq + (long)(4 * ty + i) * Dm + 4 * tx;
        #pragma unroll
        for (int j = 0; j < 4; j++) {
            float val = o[i][j] * inv;
            __half hi, lo;
            split16(val, hi, lo);
            Yh[orow + j] = hi;
            Yl[orow + j] = lo;
        }
    }
}

// ---------------------------------------------------------------------------
// Launcher
// ---------------------------------------------------------------------------
extern "C" void kernel_launch(void* const* d_in, const int* in_sizes, int n_in,
                              void* d_out, int out_size)
{
    const int*   idx  = (const int*)  d_in[0];
    const int*   ts   = (const int*)  d_in[1];
    const float* tok  = (const float*)d_in[2];
    const float* pos  = (const float*)d_in[3];
    const float* gpos = (const float*)d_in[4];
    const float* ln1w = (const float*)d_in[5];
    const float* ln1b = (const float*)d_in[6];
    const float* Wq   = (const float*)d_in[7];
    const float* bq   = (const float*)d_in[8];
    const float* Wk   = (const float*)d_in[9];
    const float* bk   = (const float*)d_in[10];
    const float* Wv   = (const float*)d_in[11];
    const float* bv   = (const float*)d_in[12];
    const float* Wo   = (const float*)d_in[13];
    const float* bo   = (const float*)d_in[14];
    const float* ln2w = (const float*)d_in[15];
    const float* ln2b = (const float*)d_in[16];
    const float* W1   = (const float*)d_in[17];
    const float* b1   = (const float*)d_in[18];
    const float* W2   = (const float*)d_in[19];
    const float* b2   = (const float*)d_in[20];
    const float* lnfw = (const float*)d_in[21];
    const float* lnfb = (const float*)d_in[22];
    const float* hw   = (const float*)d_in[23];
    float* out = (float*)d_out;

    float *x, *q, *k, *v;
    __half *pah, *pal, *pbh, *pbl, *wh, *wl;
    cudaGetSymbolAddress((void**)&x,   g_x);
    cudaGetSymbolAddress((void**)&q,   g_q);
    cudaGetSymbolAddress((void**)&k,   g_k);
    cudaGetSymbolAddress((void**)&v,   g_v);
    cudaGetSymbolAddress((void**)&pah, g_pa_h);
    cudaGetSymbolAddress((void**)&pal, g_pa_l);
    cudaGetSymbolAddress((void**)&pbh, g_pb_h);
    cudaGetSymbolAddress((void**)&pbl, g_pb_l);
    cudaGetSymbolAddress((void**)&wh,  g_wh);
    cudaGetSymbolAddress((void**)&wl,  g_wl);

    cudaFuncSetAttribute(attn_kernel, cudaFuncAttributeMaxDynamicSharedMemorySize,
                         ATT_SMEM_FLOATS * (int)sizeof(float));
    cudaFuncSetAttribute(gemm_hmma<EPI_NONE>, cudaFuncAttributeMaxDynamicSharedMemorySize, GEMM_SMEM);
    cudaFuncSetAttribute(gemm_hmma<EPI_ADD>,  cudaFuncAttributeMaxDynamicSharedMemorySize, GEMM_SMEM);
    cudaFuncSetAttribute(gemm_hmma<EPI_GELU>, cudaFuncAttributeMaxDynamicSharedMemorySize, GEMM_SMEM);

    // --- weight conversion (once per launch) ---
    auto cvt = [&](const float* src, long off, long n) {
        cvt_pair<<<(int)((n / 4 + 255) / 256), 256>>>(src, wh + off, wl + off, n);
    };
    cvt(Wq, OFF_WQ, 8L * DD);
    cvt(Wk, OFF_WK, 8L * DD);
    cvt(Wv, OFF_WV, 8L * DD);
    cvt(Wo, OFF_WO, 8L * DD);
    cvt(W1, OFF_W1, 16L * DD);
    cvt(W2, OFF_W2, 16L * DD);
    cvt(hw, OFF_HW, 8L * DD);

    embed_kernel<<<(BT * Dm) / 256, 256>>>(idx, ts, tok, pos, gpos, x);

    const dim3 gD(Dm / 128, BT / 128);
    const dim3 g2D(2 * Dm / 128, BT / 128);
    const dim3 gV(Vv / 128, BT / 128);

    for (int l = 0; l < Ll; l++) {
        layernorm_pair<<<BT, 256>>>(x, ln1w + (long)l * Dm, ln1b + (long)l * Dm, pah, pal);

        gemm_hmma<EPI_NONE><<<gD, 256, GEMM_SMEM>>>(
            pah, pal, wh + OFF_WQ + (long)l * DD, wl + OFF_WQ + (long)l * DD,
            bq + (long)l * Dm, nullptr, q, nullptr, nullptr, BT, Dm, Dm);
        gemm_hmma<EPI_NONE><<<gD, 256, GEMM_SMEM>>>(
            pah, pal, wh + OFF_WK + (long)l * DD, wl + OFF_WK + (long)l * DD,
            bk + (long)l * Dm, nullptr, k, nullptr, nullptr, BT, Dm, Dm);
        gemm_hmma<EPI_NONE><<<gD, 256, GEMM_SMEM>>>(
            pah, pal, wh + OFF_WV + (long)l * DD, wl + OFF_WV + (long)l * DD,
            bv + (long)l * Dm, nullptr, v, nullptr, nullptr, BT, Dm, Dm);

        attn_kernel<<<dim3(Tq / 64, Hh, Bq), 256,
                      ATT_SMEM_FLOATS * sizeof(float)>>>(q, k, v, pah, pal);

        gemm_hmma<EPI_ADD><<<gD, 256, GEMM_SMEM>>>(
            pah, pal, wh + OFF_WO + (long)l * DD, wl + OFF_WO + (long)l * DD,
            bo + (long)l * Dm, x, x, nullptr, nullptr, BT, Dm, Dm);

        layernorm_pair<<<BT, 256>>>(x, ln2w + (long)l * Dm, ln2b + (long)l * Dm, pah, pal);

        gemm_hmma<EPI_GELU><<<g2D, 256, GEMM_SMEM>>>(
            pah, pal, wh + OFF_W1 + (long)l * 2 * DD, wl + OFF_W1 + (long)l * 2 * DD,
            b1 + (long)l * 2 * Dm, nullptr, nullptr, pbh, pbl, BT, 2 * Dm, Dm);

        gemm_hmma<EPI_ADD><<<gD, 256, GEMM_SMEM>>>(
            pbh, pbl, wh + OFF_W2 + (long)l * 2 * DD, wl + OFF_W2 + (long)l * 2 * DD,
            b2 + (long)l * Dm, x, x, nullptr, nullptr, BT, Dm, 2 * Dm);
    }

    layernorm_pair<<<BT, 256>>>(x, lnfw, lnfb, pah, pal);
    gemm_hmma<EPI_NONE><<<gV, 256, GEMM_SMEM>>>(
        pah, pal, wh + OFF_HW, wl + OFF_HW,
        nullptr, nullptr, out, nullptr, nullptr, BT, Vv, Dm);
}

// round 5
// speedup vs baseline: 2.4581x; 1.0903x over previous
#include <cuda_runtime.h>
#include <cuda_fp16.h>
#include <math.h>
#include <stdint.h>

// ---------------------------------------------------------------------------
// Problem constants
// ---------------------------------------------------------------------------
#define Bq   8
#define Tq   1024
#define Dm   1024
#define Hh   16
#define Ll   8
#define Vv   8192
#define HD   64
#define BT   (Bq*Tq)

// ---------------------------------------------------------------------------
// Scratch (static device globals)
// ---------------------------------------------------------------------------
__device__ float g_x[BT * Dm];           // residual stream (f32)
__device__ float g_qkv[3L * BT * Dm];    // q | k | v

__device__ __half g_pa_h[BT * Dm];       // pair buf A: LN out / attn out
__device__ __half g_pa_l[BT * Dm];
__device__ __half g_pb_h[BT * 2 * Dm];   // pair buf B: MLP hidden
__device__ __half g_pb_l[BT * 2 * Dm];

#define DD      (Dm*Dm)
#define OFF_WQ  0L
#define OFF_WK  (8L*DD)
#define OFF_WV  (16L*DD)
#define OFF_WO  (24L*DD)
#define OFF_W1  (32L*DD)
#define OFF_W2  (48L*DD)
#define OFF_HW  (64L*DD)
#define WTOT    (72L*DD)
__device__ __half g_wh[WTOT];
__device__ __half g_wl[WTOT];

// ---------------------------------------------------------------------------
// Helpers
// ---------------------------------------------------------------------------
__device__ __forceinline__ uint32_t smem_u32(const void* p) {
    uint32_t a;
    asm("{ .reg .u64 t; cvta.to.shared.u64 t, %1; cvt.u32.u64 %0, t; }"
        : "=r"(a) : "l"(p));
    return a;
}
__device__ __forceinline__ void cpa16(uint32_t dst, const void* src) {
    asm volatile("cp.async.cg.shared.global [%0], [%1], 16;" :: "r"(dst), "l"(src));
}
__device__ __forceinline__ void ldm_x4(uint32_t& r0, uint32_t& r1,
                                       uint32_t& r2, uint32_t& r3, uint32_t addr) {
    asm volatile("ldmatrix.sync.aligned.m8n8.x4.shared.b16 {%0,%1,%2,%3}, [%4];"
                 : "=r"(r0), "=r"(r1), "=r"(r2), "=r"(r3) : "r"(addr));
}
__device__ __forceinline__ void mma_f16(float& d0, float& d1, float& d2, float& d3,
                                        uint32_t a0, uint32_t a1, uint32_t a2, uint32_t a3,
                                        uint32_t b0, uint32_t b1) {
    asm volatile(
        "mma.sync.aligned.m16n8k16.row.col.f32.f16.f16.f32 "
        "{%0,%1,%2,%3}, {%4,%5,%6,%7}, {%8,%9}, {%0,%1,%2,%3};"
        : "+f"(d0), "+f"(d1), "+f"(d2), "+f"(d3)
        : "r"(a0), "r"(a1), "r"(a2), "r"(a3), "r"(b0), "r"(b1));
}
__device__ __forceinline__ void split16(float x, __half& hi, __half& lo) {
    hi = __float2half_rn(x);
    lo = __float2half_rn(x - __half2float(hi));
}

// ---------------------------------------------------------------------------
// Weight f32 -> f16 hi/lo pair conversion
// ---------------------------------------------------------------------------
__global__ __launch_bounds__(256) void cvt_pair(
    const float* __restrict__ s, __half* __restrict__ h,
    __half* __restrict__ l, long n)
{
    long i = ((long)blockIdx.x * 256 + threadIdx.x) * 4;
    if (i >= n) return;
    float4 v = *(const float4*)(s + i);
    __half h0, h1, h2, h3, l0, l1, l2, l3;
    split16(v.x, h0, l0); split16(v.y, h1, l1);
    split16(v.z, h2, l2); split16(v.w, h3, l3);
    *(__half2*)(h + i)     = __halves2half2(h0, h1);
    *(__half2*)(h + i + 2) = __halves2half2(h2, h3);
    *(__half2*)(l + i)     = __halves2half2(l0, l1);
    *(__half2*)(l + i + 2) = __halves2half2(l2, l3);
}

// ---------------------------------------------------------------------------
// Embedding
// ---------------------------------------------------------------------------
__global__ __launch_bounds__(256) void embed_kernel(
    const int* __restrict__ idx, const int* __restrict__ ts,
    const float* __restrict__ tok, const float* __restrict__ pos,
    const float* __restrict__ gpos, float* __restrict__ x)
{
    long i = (long)blockIdx.x * 256 + threadIdx.x;
    int d = (int)(i % Dm);
    long bt = i / Dm;
    int t = (int)(bt % Tq);
    int b = (int)(bt / Tq);
    int tokid = idx[b * Tq + t];
    int tstep = ts[b];
    x[i] = tok[(long)tokid * Dm + d] + gpos[(long)tstep * Dm + d] + pos[(long)t * Dm + d];
}

// ---------------------------------------------------------------------------
// LayerNorm -> f16 hi/lo pair output
// ---------------------------------------------------------------------------
__global__ __launch_bounds__(256) void layernorm_pair(
    const float* __restrict__ X, const float* __restrict__ w,
    const float* __restrict__ b, __half* __restrict__ Yh, __half* __restrict__ Yl)
{
    int row = blockIdx.x;
    const float* x = X + (long)row * Dm;
    int tid = threadIdx.x;

    int i = tid * 4;
    float4 v = *(const float4*)(x + i);
    float s  = v.x + v.y + v.z + v.w;
    float ss = v.x*v.x + v.y*v.y + v.z*v.z + v.w*v.w;

    __shared__ float rs[8], rss[8];
    #pragma unroll
    for (int m = 16; m; m >>= 1) {
        s  += __shfl_xor_sync(0xffffffffu, s,  m);
        ss += __shfl_xor_sync(0xffffffffu, ss, m);
    }
    int wid = tid >> 5, lane = tid & 31;
    if (lane == 0) { rs[wid] = s; rss[wid] = ss; }
    __syncthreads();
    if (wid == 0) {
        s  = (lane < 8) ? rs[lane]  : 0.f;
        ss = (lane < 8) ? rss[lane] : 0.f;
        #pragma unroll
        for (int m = 4; m; m >>= 1) {
            s  += __shfl_xor_sync(0xffffffffu, s,  m);
            ss += __shfl_xor_sync(0xffffffffu, ss, m);
        }
        if (lane == 0) { rs[0] = s; rss[0] = ss; }
    }
    __syncthreads();
    float mean = rs[0] * (1.0f / Dm);
    float var  = rss[0] * (1.0f / Dm) - mean * mean;
    float rstd = rsqrtf(var + 1e-5f);

    float4 wv = *(const float4*)(w + i);
    float4 bv = *(const float4*)(b + i);
    float o0 = (v.x - mean) * rstd * wv.x + bv.x;
    float o1 = (v.y - mean) * rstd * wv.y + bv.y;
    float o2 = (v.z - mean) * rstd * wv.z + bv.z;
    float o3 = (v.w - mean) * rstd * wv.w + bv.w;

    long base = (long)row * Dm + i;
    __half h0, h1, h2, h3, l0, l1, l2, l3;
    split16(o0, h0, l0); split16(o1, h1, l1);
    split16(o2, h2, l2); split16(o3, h3, l3);
    *(__half2*)(Yh + base)     = __halves2half2(h0, h1);
    *(__half2*)(Yh + base + 2) = __halves2half2(h2, h3);
    *(__half2*)(Yl + base)     = __halves2half2(l0, l1);
    *(__half2*)(Yl + base + 2) = __halves2half2(l2, l3);
}

// ---------------------------------------------------------------------------
// HMMA GEMM (3x f16 split), ldmatrix fragment loads.
// C[m,n] = sum_k A[m,k]*B[n,k]; epilogues: NONE / ADD residual / GELU->pair /
// QKV (fused q,k,v: B rows span 3 matrices with uniform stride bStride;
// output -> C + sel*BT*Dm, bias selected from b0/b1/b2).
// CTA 128x128, k-step 32, cp.async double buffer, 8 warps of 64x32.
// ---------------------------------------------------------------------------
#define EPI_NONE 0
#define EPI_ADD  1
#define EPI_GELU 2
#define EPI_QKV  3

#define PK      40
#define TILE_H  (128*PK)
#define STG_H   (4*TILE_H)
#define GEMM_SMEM (2*STG_H*2)

template<int EPI>
__global__ __launch_bounds__(256, 2) void gemm_hmma(
    const __half* __restrict__ Ah, const __half* __restrict__ Al,
    const __half* __restrict__ Bh, const __half* __restrict__ Bl,
    long bStride,
    const float* __restrict__ b0p, const float* __restrict__ b1p,
    const float* __restrict__ b2p, const float* __restrict__ res,
    float* __restrict__ C, __half* __restrict__ Ch, __half* __restrict__ Cl,
    int M, int N, int K)
{
    extern __shared__ __align__(16) __half gsm[];
    const uint32_t sbase = smem_u32(gsm);

    const int tid = threadIdx.x, lane = tid & 31, warp = tid >> 5;
    const int g = lane >> 2, t = lane & 3, l7 = lane & 7;
    const int wm = warp & 1, wn = warp >> 1;
    const int m0 = blockIdx.y * 128, n0 = blockIdx.x * 128;

    float acc[4][4][4];
    #pragma unroll
    for (int a = 0; a < 4; a++)
        #pragma unroll
        for (int b = 0; b < 4; b++)
            #pragma unroll
            for (int c = 0; c < 4; c++) acc[a][b][c] = 0.f;

    const int S = K >> 5;

    auto issue = [&](int k0, int buf) {
        #pragma unroll
        for (int j = 0; j < 8; j++) {
            int c = tid + 256 * j;
            int tile = c >> 9;
            int r = (c >> 2) & 127;
            int q = c & 3;
            const __half* src;
            if (tile == 0)      src = Ah + (long)(m0 + r) * K + k0 + q * 8;
            else if (tile == 1) src = Al + (long)(m0 + r) * K + k0 + q * 8;
            else {
                long roff;
                if (EPI == EPI_QKV) {
                    int rg = n0 + r;
                    roff = (long)(rg >> 10) * bStride + (long)(rg & 1023) * K;
                } else {
                    roff = (long)(n0 + r) * K;
                }
                src = (tile == 2 ? Bh : Bl) + roff + k0 + q * 8;
            }
            uint32_t dst = sbase + (uint32_t)(buf * STG_H + tile * TILE_H + r * PK + q * 8) * 2u;
            cpa16(dst, src);
        }
        asm volatile("cp.async.commit_group;" ::: "memory");
    };

    issue(0, 0);

    for (int s = 0; s < S; s++) {
        asm volatile("cp.async.wait_group 0;" ::: "memory");
        __syncthreads();
        if (s + 1 < S) issue((s + 1) << 5, (s + 1) & 1);

        uint32_t sb  = sbase + (uint32_t)((s & 1) * STG_H) * 2u;
        uint32_t A_h = sb;
        uint32_t A_l = sb + TILE_H * 2u;
        uint32_t B_h = sb + 2u * TILE_H * 2u;
        uint32_t B_l = sb + 3u * TILE_H * 2u;

        #pragma unroll
        for (int kk = 0; kk < 32; kk += 16) {
            uint32_t bh[4][2], bl[4][2];
            #pragma unroll
            for (int p = 0; p < 2; p++) {
                int row = wn * 32 + p * 16 + l7 + ((lane & 16) >> 1);
                int kc  = kk + (lane & 8);
                uint32_t off = (uint32_t)(row * PK + kc) * 2u;
                ldm_x4(bh[2*p][0], bh[2*p][1], bh[2*p+1][0], bh[2*p+1][1], B_h + off);
                ldm_x4(bl[2*p][0], bl[2*p][1], bl[2*p+1][0], bl[2*p+1][1], B_l + off);
            }
            #pragma unroll
            for (int mi = 0; mi < 4; mi++) {
                int row = wm * 64 + mi * 16 + l7 + (lane & 8);
                int kc  = kk + ((lane & 16) >> 1);
                uint32_t off = (uint32_t)(row * PK + kc) * 2u;
                uint32_t ah0, ah1, ah2, ah3, al0, al1, al2, al3;
                ldm_x4(ah0, ah1, ah2, ah3, A_h + off);
                ldm_x4(al0, al1, al2, al3, A_l + off);
                #pragma unroll
                for (int ni = 0; ni < 4; ni++) {
                    float* d = acc[mi][ni];
                    mma_f16(d[0], d[1], d[2], d[3], ah0, ah1, ah2, ah3, bh[ni][0], bh[ni][1]);
                    mma_f16(d[0], d[1], d[2], d[3], ah0, ah1, ah2, ah3, bl[ni][0], bl[ni][1]);
                    mma_f16(d[0], d[1], d[2], d[3], al0, al1, al2, al3, bh[ni][0], bh[ni][1]);
                }
            }
        }
    }

    // --- epilogue ---
    const float* bias = b0p;
    float* Cd = C;
    int csub = 0, Nw = N;
    if (EPI == EPI_QKV) {
        int sel = n0 >> 10;
        bias = (sel == 0) ? b0p : (sel == 1) ? b1p : b2p;
        Cd = C + (long)sel * BT * Dm;
        csub = sel << 10;
        Nw = Dm;
    }

    #pragma unroll
    for (int mi = 0; mi < 4; mi++) {
        int r0 = m0 + wm * 64 + mi * 16 + g;
        #pragma unroll
        for (int ni = 0; ni < 4; ni++) {
            int cc = n0 + wn * 32 + ni * 8 + 2 * t;
            float b0v = bias ? bias[cc - csub] : 0.f;
            float b1v = bias ? bias[cc - csub + 1] : 0.f;
            float v0 = acc[mi][ni][0] + b0v, v1 = acc[mi][ni][1] + b1v;
            float v2 = acc[mi][ni][2] + b0v, v3 = acc[mi][ni][3] + b1v;
            long i0 = (long)r0 * Nw + (cc - csub);
            long i1 = (long)(r0 + 8) * Nw + (cc - csub);
            if (EPI == EPI_ADD) {
                v0 += res[i0]; v1 += res[i0 + 1];
                v2 += res[i1]; v3 += res[i1 + 1];
            }
            if (EPI == EPI_GELU) {
                v0 = 0.5f * v0 * (1.f + erff(v0 * 0.70710678118654752f));
                v1 = 0.5f * v1 * (1.f + erff(v1 * 0.70710678118654752f));
                v2 = 0.5f * v2 * (1.f + erff(v2 * 0.70710678118654752f));
                v3 = 0.5f * v3 * (1.f + erff(v3 * 0.70710678118654752f));
                __half h0, h1, h2, h3, l0, l1, l2, l3;
                split16(v0, h0, l0); split16(v1, h1, l1);
                split16(v2, h2, l2); split16(v3, h3, l3);
                *(__half2*)(Ch + i0) = __halves2half2(h0, h1);
                *(__half2*)(Ch + i1) = __halves2half2(h2, h3);
                *(__half2*)(Cl + i0) = __halves2half2(l0, l1);
                *(__half2*)(Cl + i1) = __halves2half2(l2, l3);
            } else {
                *(float2*)(Cd + i0) = make_float2(v0, v1);
                *(float2*)(Cd + i1) = make_float2(v2, v3);
            }
        }
    }
}

// ---------------------------------------------------------------------------
// Flash attention (fp32, causal) -> f16 hi/lo pair output
// ---------------------------------------------------------------------------
#define APAD 68
#define ATT_SMEM_FLOATS (4 * 64 * APAD)

__global__ __launch_bounds__(256) void attn_kernel(
    const float* __restrict__ Q, const float* __restrict__ K,
    const float* __restrict__ V, __half* __restrict__ Yh, __half* __restrict__ Yl)
{
    extern __shared__ float smem[];
    float (*Qs)[APAD]  = (float (*)[APAD])(smem);
    float (*Kst)[APAD] = (float (*)[APAD])(smem + 64 * APAD);
    float (*Vs)[APAD]  = (float (*)[APAD])(smem + 2 * 64 * APAD);
    float (*Ps)[APAD]  = (float (*)[APAD])(smem + 3 * 64 * APAD);

    const int qt = blockIdx.x, h = blockIdx.y, b = blockIdx.z;
    const int tid = threadIdx.x;
    const int tx = tid & 15;
    const int ty = tid >> 4;

    const long baseq = ((long)(b * Tq + qt * 64)) * Dm + h * HD;

    for (int i = tid; i < 64 * 16; i += 256) {
        int r = i >> 4, c4 = (i & 15) << 2;
        float4 v = *(const float4*)(Q + baseq + (long)r * Dm + c4);
        Qs[r][c4] = v.x; Qs[r][c4 + 1] = v.y; Qs[r][c4 + 2] = v.z; Qs[r][c4 + 3] = v.w;
    }

    float m_i[4], l_i[4], o[4][4];
    #pragma unroll
    for (int i = 0; i < 4; i++) {
        m_i[i] = -1e30f; l_i[i] = 0.f;
        #pragma unroll
        for (int j = 0; j < 4; j++) o[i][j] = 0.f;
    }

    for (int kt = 0; kt <= qt; kt++) {
        const long basek = ((long)(b * Tq + kt * 64)) * Dm + h * HD;
        for (int i = tid; i < 64 * 16; i += 256) {
            int r = i >> 4, c4 = (i & 15) << 2;
            float4 kv = *(const float4*)(K + basek + (long)r * Dm + c4);
            Kst[c4][r] = kv.x; Kst[c4 + 1][r] = kv.y; Kst[c4 + 2][r] = kv.z; Kst[c4 + 3][r] = kv.w;
            float4 vv = *(const float4*)(V + basek + (long)r * Dm + c4);
            Vs[r][c4] = vv.x; Vs[r][c4 + 1] = vv.y; Vs[r][c4 + 2] = vv.z; Vs[r][c4 + 3] = vv.w;
        }
        __syncthreads();

        float s[4][4];
        #pragma unroll
        for (int i = 0; i < 4; i++)
            #pragma unroll
            for (int j = 0; j < 4; j++) s[i][j] = 0.f;

        #pragma unroll 8
        for (int kk = 0; kk < 64; kk++) {
            float a0 = Qs[4 * ty + 0][kk];
            float a1 = Qs[4 * ty + 1][kk];
            float a2 = Qs[4 * ty + 2][kk];
            float a3 = Qs[4 * ty + 3][kk];
            float4 bb = *(const float4*)&Kst[kk][4 * tx];
            s[0][0] = fmaf(a0, bb.x, s[0][0]); s[0][1] = fmaf(a0, bb.y, s[0][1]);
            s[0][2] = fmaf(a0, bb.z, s[0][2]); s[0][3] = fmaf(a0, bb.w, s[0][3]);
            s[1][0] = fmaf(a1, bb.x, s[1][0]); s[1][1] = fmaf(a1, bb.y, s[1][1]);
            s[1][2] = fmaf(a1, bb.z, s[1][2]); s[1][3] = fmaf(a1, bb.w, s[1][3]);
            s[2][0] = fmaf(a2, bb.x, s[2][0]); s[2][1] = fmaf(a2, bb.y, s[2][1]);
            s[2][2] = fmaf(a2, bb.z, s[2][2]); s[2][3] = fmaf(a2, bb.w, s[2][3]);
            s[3][0] = fmaf(a3, bb.x, s[3][0]); s[3][1] = fmaf(a3, bb.y, s[3][1]);
            s[3][2] = fmaf(a3, bb.z, s[3][2]); s[3][3] = fmaf(a3, bb.w, s[3][3]);
        }

        const float scale = 0.125f;
        #pragma unroll
        for (int i = 0; i < 4; i++)
            #pragma unroll
            for (int j = 0; j < 4; j++) s[i][j] *= scale;

        if (kt == qt) {
            #pragma unroll
            for (int i = 0; i < 4; i++)
                #pragma unroll
                for (int j = 0; j < 4; j++)
                    if (4 * tx + j > 4 * ty + i) s[i][j] = -1e30f;
        }

        #pragma unroll
        for (int i = 0; i < 4; i++) {
            float rmax = fmaxf(fmaxf(s[i][0], s[i][1]), fmaxf(s[i][2], s[i][3]));
            #pragma unroll
            for (int m = 8; m; m >>= 1)
                rmax = fmaxf(rmax, __shfl_xor_sync(0xffffffffu, rmax, m));
            float mnew  = fmaxf(m_i[i], rmax);
            float alpha = expf(m_i[i] - mnew);
            m_i[i] = mnew;
            float rsum = 0.f;
            #pragma unroll
            for (int j = 0; j < 4; j++) {
                float p = expf(s[i][j] - mnew);
                s[i][j] = p;
                rsum += p;
            }
            #pragma unroll
            for (int m = 8; m; m >>= 1)
                rsum += __shfl_xor_sync(0xffffffffu, rsum, m);
            l_i[i] = l_i[i] * alpha + rsum;
            #pragma unroll
            for (int j = 0; j < 4; j++) o[i][j] *= alpha;
        }

        #pragma unroll
        for (int i = 0; i < 4; i++)
            #pragma unroll
            for (int j = 0; j < 4; j++)
                Ps[4 * ty + i][4 * tx + j] = s[i][j];
        __syncthreads();

        #pragma unroll 8
        for (int kk = 0; kk < 64; kk++) {
            float a0 = Ps[4 * ty + 0][kk];
            float a1 = Ps[4 * ty + 1][kk];
            float a2 = Ps[4 * ty + 2][kk];
            float a3 = Ps[4 * ty + 3][kk];
            float4 bb = *(const float4*)&Vs[kk][4 * tx];
            o[0][0] = fmaf(a0, bb.x, o[0][0]); o[0][1] = fmaf(a0, bb.y, o[0][1]);
            o[0][2] = fmaf(a0, bb.z, o[0][2]); o[0][3] = fmaf(a0, bb.w, o[0][3]);
            o[1][0] = fmaf(a1, bb.x, o[1][0]); o[1][1] = fmaf(a1, bb.y, o[1][1]);
            o[1][2] = fmaf(a1, bb.z, o[1][2]); o[1][3] = fmaf(a1, bb.w, o[1][3]);
            o[2][0] = fmaf(a2, bb.x, o[2][0]); o[2][1] = fmaf(a2, bb.y, o[2][1]);
            o[2][2] = fmaf(a2, bb.z, o[2][2]); o[2][3] = fmaf(a2, bb.w, o[2][3]);
            o[3][0] = fmaf(a3, bb.x, o[3][0]); o[3][1] = fmaf(a3, bb.y, o[3][1]);
            o[3][2] = fmaf(a3, bb.z, o[3][2]); o[3][3] = fmaf(a3, bb.w, o[3][3]);
        }
        __syncthreads();
    }

    #pragma unroll
    for (int i = 0; i < 4; i++) {
        float inv = 1.f / l_i[i];
        long orow = baseq + (long)(4 * ty + i) * Dm + 4 * tx;
        #pragma unroll
        for (int j = 0; j < 4; j++) {
            float val = o[i][j] * inv;
            __half hi, lo;
            split16(val, hi, lo);
            Yh[orow + j] = hi;
            Yl[orow + j] = lo;
        }
    }
}

// ---------------------------------------------------------------------------
// Launcher
// ---------------------------------------------------------------------------
extern "C" void kernel_launch(void* const* d_in, const int* in_sizes, int n_in,
                              void* d_out, int out_size)
{
    const int*   idx  = (const int*)  d_in[0];
    const int*   ts   = (const int*)  d_in[1];
    const float* tok  = (const float*)d_in[2];
    const float* pos  = (const float*)d_in[3];
    const float* gpos = (const float*)d_in[4];
    const float* ln1w = (const float*)d_in[5];
    const float* ln1b = (const float*)d_in[6];
    const float* Wq   = (const float*)d_in[7];
    const float* bq   = (const float*)d_in[8];
    const float* Wk   = (const float*)d_in[9];
    const float* bk   = (const float*)d_in[10];
    const float* Wv   = (const float*)d_in[11];
    const float* bv   = (const float*)d_in[12];
    const float* Wo   = (const float*)d_in[13];
    const float* bo   = (const float*)d_in[14];
    const float* ln2w = (const float*)d_in[15];
    const float* ln2b = (const float*)d_in[16];
    const float* W1   = (const float*)d_in[17];
    const float* b1   = (const float*)d_in[18];
    const float* W2   = (const float*)d_in[19];
    const float* b2   = (const float*)d_in[20];
    const float* lnfw = (const float*)d_in[21];
    const float* lnfb = (const float*)d_in[22];
    const float* hw   = (const float*)d_in[23];
    float* out = (float*)d_out;

    float *x, *qkv;
    __half *pah, *pal, *pbh, *pbl, *wh, *wl;
    cudaGetSymbolAddress((void**)&x,   g_x);
    cudaGetSymbolAddress((void**)&qkv, g_qkv);
    cudaGetSymbolAddress((void**)&pah, g_pa_h);
    cudaGetSymbolAddress((void**)&pal, g_pa_l);
    cudaGetSymbolAddress((void**)&pbh, g_pb_h);
    cudaGetSymbolAddress((void**)&pbl, g_pb_l);
    cudaGetSymbolAddress((void**)&wh,  g_wh);
    cudaGetSymbolAddress((void**)&wl,  g_wl);

    cudaFuncSetAttribute(attn_kernel, cudaFuncAttributeMaxDynamicSharedMemorySize,
                         ATT_SMEM_FLOATS * (int)sizeof(float));
    cudaFuncSetAttribute(gemm_hmma<EPI_NONE>, cudaFuncAttributeMaxDynamicSharedMemorySize, GEMM_SMEM);
    cudaFuncSetAttribute(gemm_hmma<EPI_ADD>,  cudaFuncAttributeMaxDynamicSharedMemorySize, GEMM_SMEM);
    cudaFuncSetAttribute(gemm_hmma<EPI_GELU>, cudaFuncAttributeMaxDynamicSharedMemorySize, GEMM_SMEM);
    cudaFuncSetAttribute(gemm_hmma<EPI_QKV>,  cudaFuncAttributeMaxDynamicSharedMemorySize, GEMM_SMEM);

    auto cvt = [&](const float* src, long off, long n) {
        cvt_pair<<<(int)((n / 4 + 255) / 256), 256>>>(src, wh + off, wl + off, n);
    };
    cvt(Wq, OFF_WQ, 8L * DD);
    cvt(Wk, OFF_WK, 8L * DD);
    cvt(Wv, OFF_WV, 8L * DD);
    cvt(Wo, OFF_WO, 8L * DD);
    cvt(W1, OFF_W1, 16L * DD);
    cvt(W2, OFF_W2, 16L * DD);
    cvt(hw, OFF_HW, 8L * DD);

    embed_kernel<<<(BT * Dm) / 256, 256>>>(idx, ts, tok, pos, gpos, x);

    const dim3 gD(Dm / 128, BT / 128);
    const dim3 gQKV(3 * Dm / 128, BT / 128);
    const dim3 g2D(2 * Dm / 128, BT / 128);
    const dim3 gV(Vv / 128, BT / 128);

    float* qb = qkv;
    float* kb = qkv + (long)BT * Dm;
    float* vb = qkv + 2L * BT * Dm;

    for (int l = 0; l < Ll; l++) {
        layernorm_pair<<<BT, 256>>>(x, ln1w + (long)l * Dm, ln1b + (long)l * Dm, pah, pal);

        gemm_hmma<EPI_QKV><<<gQKV, 256, GEMM_SMEM>>>(
            pah, pal, wh + OFF_WQ + (long)l * DD, wl + OFF_WQ + (long)l * DD,
            8L * DD,
            bq + (long)l * Dm, bk + (long)l * Dm, bv + (long)l * Dm,
            nullptr, qkv, nullptr, nullptr, BT, 3 * Dm, Dm);

        attn_kernel<<<dim3(Tq / 64, Hh, Bq), 256,
                      ATT_SMEM_FLOATS * sizeof(float)>>>(qb, kb, vb, pah, pal);

        gemm_hmma<EPI_ADD><<<gD, 256, GEMM_SMEM>>>(
            pah, pal, wh + OFF_WO + (long)l * DD, wl + OFF_WO + (long)l * DD, 0,
            bo + (long)l * Dm, nullptr, nullptr, x, x, nullptr, nullptr, BT, Dm, Dm);

        layernorm_pair<<<BT, 256>>>(x, ln2w + (long)l * Dm, ln2b + (long)l * Dm, pah, pal);

        gemm_hmma<EPI_GELU><<<g2D, 256, GEMM_SMEM>>>(
            pah, pal, wh + OFF_W1 + (long)l * 2 * DD, wl + OFF_W1 + (long)l * 2 * DD, 0,
            b1 + (long)l * 2 * Dm, nullptr, nullptr, nullptr,
            nullptr, pbh, pbl, BT, 2 * Dm, Dm);

        gemm_hmma<EPI_ADD><<<gD, 256, GEMM_SMEM>>>(
            pbh, pbl, wh + OFF_W2 + (long)l * 2 * DD, wl + OFF_W2 + (long)l * 2 * DD, 0,
            b2 + (long)l * Dm, nullptr, nullptr, x, x, nullptr, nullptr, BT, Dm, 2 * Dm);
    }

    layernorm_pair<<<BT, 256>>>(x, lnfw, lnfb, pah, pal);
    gemm_hmma<EPI_NONE><<<gV, 256, GEMM_SMEM>>>(
        pah, pal, wh + OFF_HW, wl + OFF_HW, 0,
        nullptr, nullptr, nullptr, nullptr, out, nullptr, nullptr, BT, Vv, Dm);
}